// round 16
// baseline (speedup 1.0000x reference)
#include <cuda_runtime.h>
#include <math.h>

// MoE router, fp32 f32x2 SIMT, t4e16: 4 tokens x 16 experts per thread.
// warp = 128 tokens x 16 experts; 16 warps = 4 expert-groups x 4 k-phases.
// BM=128, 512 threads, grid 128, fused softmax/top2 epilogue.
// x: [16384, 2048] f32, W: [2048, 64] f32
// out (f32): dispatch[16384*64], probs[16384*64], tkp[16384*2], tki[16384*2]

#define M_TOK   16384
#define K_DIM   2048
#define N_EXP   64
#define BM      128
#define BK      64
#define NT      (K_DIM / BK)          // 32
#define THREADS 512

// stage (floats): xs [128 tok][68] (64 k + 4 pad), ws [64 k][64 e]
#define XS_STRIDE    68
#define XS_FLOATS    (BM * XS_STRIDE)          // 8704
#define WS_OFF       XS_FLOATS
#define STAGE_FLOATS (XS_FLOATS + BK * N_EXP)  // 12800
#define SMEM_BYTES   (2 * STAGE_FLOATS * 4)    // 102400 B

// epilogue: two logits buffers [128][66] aliasing the (then-free) GEMM stages
#define LG_STRIDE 66
#define LGB_OFF   8448                         // 128*66

#define OFF_DISP  0
#define OFF_PROBS (M_TOK * N_EXP)
#define OFF_TKP   (2 * M_TOK * N_EXP)
#define OFF_TKI   (2 * M_TOK * N_EXP + 2 * M_TOK)

__device__ __forceinline__ unsigned long long pack2(float v) {
    unsigned long long r;
    asm("mov.b64 %0, {%1, %1};" : "=l"(r) : "f"(v));
    return r;
}
__device__ __forceinline__ void ffma2(unsigned long long& c, unsigned long long a,
                                      unsigned long long b) {
    asm("fma.rn.f32x2 %0, %1, %2, %0;" : "+l"(c) : "l"(a), "l"(b));
}
__device__ __forceinline__ unsigned long long add2(unsigned long long a,
                                                   unsigned long long b) {
    unsigned long long r;
    asm("add.rn.f32x2 %0, %1, %2;" : "=l"(r) : "l"(a), "l"(b));
    return r;
}
__device__ __forceinline__ void cp16(unsigned dst, const void* src) {
    asm volatile("cp.async.cg.shared.global [%0], [%1], 16;\n" :: "r"(dst), "l"(src));
}
#define CP_COMMIT() asm volatile("cp.async.commit_group;\n" ::: "memory")
#define CP_WAIT0()  asm volatile("cp.async.wait_group 0;\n" ::: "memory")

__global__ __launch_bounds__(THREADS, 1)
void moe_router_kernel(const float* __restrict__ x,
                       const float* __restrict__ W,
                       float* __restrict__ out) {
    extern __shared__ float sm[];
    __shared__ float s_max[BM], s_inv[BM];
    __shared__ int   s_i1[BM], s_i2[BM];

    const int t    = threadIdx.x;
    const int wid  = t >> 5;
    const int lane = t & 31;
    const int kp   = wid >> 2;        // k-phase 0..3 (16 k each per 64-k tile)
    const int e0   = (wid & 3) * 16;  // expert group: 16 experts
    const int tok0 = blockIdx.x * BM;
    const unsigned smb = (unsigned)__cvta_generic_to_shared(sm);

    // cp.async mappings
    // x: 128 tok x 64 k = 2048 uint4; 4 per thread
    int xa_tok[4], xa_c[4];
#pragma unroll
    for (int r = 0; r < 4; r++) {
        int idx = t + r * THREADS;
        xa_tok[r] = idx >> 4;         // 0..127
        xa_c[r]   = idx & 15;         // uint4 within 64-k row
    }
    // W: 64 k x 64 e = 1024 uint4; 2 per thread
    int wa_k[2], wa_c[2];
#pragma unroll
    for (int r = 0; r < 2; r++) {
        int idx = t + r * THREADS;    // 0..1023
        wa_k[r] = idx >> 4;           // 0..63 (k row)
        wa_c[r] = idx & 15;           // uint4 within 64-e row
    }

    unsigned long long acc[4][8];     // [token c][expert pair j]
#pragma unroll
    for (int c = 0; c < 4; c++)
#pragma unroll
        for (int j = 0; j < 8; j++) acc[c][j] = 0ull;

    // ---- prologue: stage 0 ----
#pragma unroll
    for (int r = 0; r < 4; r++)
        cp16(smb + (unsigned)(xa_tok[r] * XS_STRIDE + xa_c[r] * 4) * 4,
             x + (size_t)(tok0 + xa_tok[r]) * K_DIM + xa_c[r] * 4);
#pragma unroll
    for (int r = 0; r < 2; r++)
        cp16(smb + (unsigned)(WS_OFF + wa_k[r] * N_EXP + wa_c[r] * 4) * 4,
             W + (size_t)wa_k[r] * N_EXP + wa_c[r] * 4);
    CP_COMMIT();

#pragma unroll 1
    for (int kt = 0; kt < NT; kt++) {
        const int s = kt & 1;
        CP_WAIT0();
        __syncthreads();

        // prefetch tile kt+1 into the other stage (free since iter kt-1)
        if (kt + 1 < NT) {
            const int sn = s ^ 1;
            const int kb = (kt + 1) * BK;
            const unsigned sb = smb + (unsigned)(sn * STAGE_FLOATS) * 4;
#pragma unroll
            for (int r = 0; r < 4; r++)
                cp16(sb + (unsigned)(xa_tok[r] * XS_STRIDE + xa_c[r] * 4) * 4,
                     x + (size_t)(tok0 + xa_tok[r]) * K_DIM + kb + xa_c[r] * 4);
#pragma unroll
            for (int r = 0; r < 2; r++)
                cp16(sb + (unsigned)(WS_OFF + wa_k[r] * N_EXP + wa_c[r] * 4) * 4,
                     W + (size_t)(kb + wa_k[r]) * N_EXP + wa_c[r] * 4);
            CP_COMMIT();
        }

        // ---- compute stage s: this warp's 16-k quarter (kp) ----
        const float* xs = sm + s * STAGE_FLOATS + kp * 16;
        const float* ws = sm + s * STAGE_FLOATS + WS_OFF + kp * 16 * N_EXP + e0;

#pragma unroll
        for (int k4 = 0; k4 < 4; k4++) {
            float4 xv[4];
#pragma unroll
            for (int c = 0; c < 4; c++)
                xv[c] = *reinterpret_cast<const float4*>(
                    xs + (lane + 32 * c) * XS_STRIDE + k4 * 4);
#pragma unroll
            for (int kk = 0; kk < 4; kk++) {
                const float* wrow = ws + (k4 * 4 + kk) * N_EXP;
                ulonglong2 wA = *reinterpret_cast<const ulonglong2*>(wrow);
                ulonglong2 wB = *reinterpret_cast<const ulonglong2*>(wrow + 4);
                ulonglong2 wC = *reinterpret_cast<const ulonglong2*>(wrow + 8);
                ulonglong2 wD = *reinterpret_cast<const ulonglong2*>(wrow + 12);
#pragma unroll
                for (int c = 0; c < 4; c++) {
                    float xk = (kk == 0) ? xv[c].x : (kk == 1) ? xv[c].y
                             : (kk == 2) ? xv[c].z : xv[c].w;
                    unsigned long long a = pack2(xk);
                    ffma2(acc[c][0], a, wA.x);
                    ffma2(acc[c][1], a, wA.y);
                    ffma2(acc[c][2], a, wB.x);
                    ffma2(acc[c][3], a, wB.y);
                    ffma2(acc[c][4], a, wC.x);
                    ffma2(acc[c][5], a, wC.y);
                    ffma2(acc[c][6], a, wD.x);
                    ffma2(acc[c][7], a, wD.y);
                }
            }
        }
        // no trailing sync: next iter's CP_WAIT0 + __syncthreads covers it
    }

    // ---- 4-phase reduction into lgA/lgB (GEMM stages free now) ----
    float* lgA = sm;
    float* lgB = sm + LGB_OFF;
    if (kp == 1 || kp == 3) {
        float* dst = (kp == 1) ? lgA : lgB;
#pragma unroll
        for (int c = 0; c < 4; c++) {
            int tok = lane + 32 * c;
#pragma unroll
            for (int j = 0; j < 8; j++)
                *reinterpret_cast<unsigned long long*>(
                    dst + tok * LG_STRIDE + e0 + 2 * j) = acc[c][j];
        }
    }
    __syncthreads();
    if (kp == 0 || kp == 2) {
        float* dst = (kp == 0) ? lgA : lgB;
#pragma unroll
        for (int c = 0; c < 4; c++) {
            int tok = lane + 32 * c;
#pragma unroll
            for (int j = 0; j < 8; j++) {
                unsigned long long* p = reinterpret_cast<unsigned long long*>(
                    dst + tok * LG_STRIDE + e0 + 2 * j);
                *p = add2(*p, acc[c][j]);
            }
        }
    }
    __syncthreads();

    // ---- phase 1: per-token max / top-2 / softmax denom (row = A+B) ----
    if (t < BM) {
        const float* rA = lgA + t * LG_STRIDE;
        const float* rB = lgB + t * LG_STRIDE;
        float b1 = -INFINITY, b2 = -INFINITY;
        int i1 = 0, i2 = 0;
#pragma unroll
        for (int e = 0; e < N_EXP; e++) {
            float v = rA[e] + rB[e];
            if (v > b1)      { b2 = b1; i2 = i1; b1 = v; i1 = e; }
            else if (v > b2) { b2 = v;  i2 = e; }
        }
        float ssum = 0.f;
#pragma unroll
        for (int e = 0; e < N_EXP; e++) ssum += __expf(rA[e] + rB[e] - b1);
        float inv = 1.f / ssum;
        s_max[t] = b1; s_inv[t] = inv; s_i1[t] = i1; s_i2[t] = i2;

        int gtok = tok0 + t;
        out[OFF_TKP + gtok * 2 + 0] = inv;
        out[OFF_TKP + gtok * 2 + 1] = __expf(b2 - b1) * inv;
        out[OFF_TKI + gtok * 2 + 0] = (float)i1;
        out[OFF_TKI + gtok * 2 + 1] = (float)i2;
    }
    __syncthreads();

    // ---- phase 2: coalesced probs + dispatch ----
#pragma unroll
    for (int idx = t; idx < BM * N_EXP; idx += THREADS) {
        int tok = idx >> 6;
        int e   = idx & 63;
        float v = lgA[tok * LG_STRIDE + e] + lgB[tok * LG_STRIDE + e];
        float p = __expf(v - s_max[tok]) * s_inv[tok];
        int gtok = tok0 + tok;
        out[OFF_PROBS + (size_t)gtok * N_EXP + e] = p;
        out[OFF_DISP  + (size_t)gtok * N_EXP + e] =
            (e == s_i1[tok] || e == s_i2[tok]) ? 1.f : 0.f;
    }
}

extern "C" void kernel_launch(void* const* d_in, const int* in_sizes, int n_in,
                              void* d_out, int out_size) {
    const float* x = (const float*)d_in[0];
    const float* W = (const float*)d_in[1];
    float* out = (float*)d_out;

    static bool attr_set = false;
    if (!attr_set) {
        cudaFuncSetAttribute(moe_router_kernel,
                             cudaFuncAttributeMaxDynamicSharedMemorySize, SMEM_BYTES);
        attr_set = true;
    }
    moe_router_kernel<<<M_TOK / BM, THREADS, SMEM_BYTES>>>(x, W, out);
}